// round 2
// baseline (speedup 1.0000x reference)
#include <cuda_runtime.h>

// out[b,t,:] = ((vf[b] @ Wv + bv) @ Wp + bp)  broadcast over t
// (softmax over identical keys is uniform -> y == v; independent of x/Wq/Wk).
//
// 4-kernel pipeline, all reductions fixed-order (deterministic):
//  1) ca_gemm1  : part1[p][b][c] = sum_{k in chunk p} vf[b,k]*Wv[k,c]   (Wv read ONCE)
//  2) ca_gemm2  : reduce part1 -> vv chunk (smem tree), part2 = vv_chunk @ Wp_chunk
//  3) ca_reduce2: r[b][c] = bp[c] + sum_p part2[p][b][c]    (tiny, L2-resident)
//  4) ca_bcast  : stream r to all T rows (16 MB write at full BW)

#define B_   4
#define T_   1024
#define C_   1024
#define KS_  128     // split-K chunks
#define KCH_ 8       // k rows per chunk (KS_*KCH_ == C_)
#define TT_  8       // T rows per broadcast block

__device__ float g_part1[KS_ * B_ * C_];   // 2 MB
__device__ float g_part2[KS_ * B_ * C_];   // 2 MB
__device__ float g_r[B_ * C_];             // 16 KB

// ---------------------------------------------------------------------------
// Kernel 1: split-K  vf[B,C] @ Wv[C,C], all 4 batches per block.
// grid KS_, block 256 (thread = one float4 column group, 16 accumulators)
// ---------------------------------------------------------------------------
__global__ void ca_gemm1(const float* __restrict__ vf,
                         const float* __restrict__ Wv) {
    __shared__ float s_vf[KCH_ * B_];
    const int ks = blockIdx.x;
    const int k0 = ks * KCH_;
    const int tid = threadIdx.x;

    if (tid < KCH_ * B_) {
        const int kk = tid / B_, b = tid % B_;
        s_vf[tid] = vf[b * C_ + k0 + kk];
    }
    __syncthreads();

    const int c4 = tid * 4;
    float4 acc[B_];
#pragma unroll
    for (int b = 0; b < B_; b++) acc[b] = make_float4(0.f, 0.f, 0.f, 0.f);

#pragma unroll
    for (int kk = 0; kk < KCH_; kk++) {
        const float4 w =
            *reinterpret_cast<const float4*>(&Wv[(k0 + kk) * C_ + c4]);
#pragma unroll
        for (int b = 0; b < B_; b++) {
            const float a = s_vf[kk * B_ + b];
            acc[b].x += a * w.x;
            acc[b].y += a * w.y;
            acc[b].z += a * w.z;
            acc[b].w += a * w.w;
        }
    }
#pragma unroll
    for (int b = 0; b < B_; b++)
        *reinterpret_cast<float4*>(&g_part1[(ks * B_ + b) * C_ + c4]) = acc[b];
}

// ---------------------------------------------------------------------------
// Kernel 2: reduce part1 chunk (fixed-order tree) + bv, then split-K @ Wp.
// grid KS_, block 256
// ---------------------------------------------------------------------------
__global__ void ca_gemm2(const float* __restrict__ bv,
                         const float* __restrict__ Wp) {
    __shared__ float s_red[KCH_ * B_][8];   // 32 pairs x 8 partial sums
    __shared__ float s_vv[KCH_ * B_];
    const int ks = blockIdx.x;
    const int k0 = ks * KCH_;
    const int tid = threadIdx.x;

    // 32 (kk,b) pairs, 8 threads each sum 16 partials
    {
        const int pair = tid >> 3;          // 0..31
        const int sub  = tid & 7;
        const int kk = pair >> 2, b = pair & 3;
        float s = 0.f;
#pragma unroll
        for (int i = 0; i < 16; i++) {
            const int p = sub * 16 + i;
            s += g_part1[(p * B_ + b) * C_ + k0 + kk];
        }
        s_red[pair][sub] = s;
    }
    __syncthreads();
    if (tid < KCH_ * B_) {
        const int kk = tid >> 2;
        float s = bv[k0 + kk];
#pragma unroll
        for (int j = 0; j < 8; j++) s += s_red[tid][j];
        s_vv[tid] = s;
    }
    __syncthreads();

    const int c4 = tid * 4;
    float4 acc[B_];
#pragma unroll
    for (int b = 0; b < B_; b++) acc[b] = make_float4(0.f, 0.f, 0.f, 0.f);

#pragma unroll
    for (int kk = 0; kk < KCH_; kk++) {
        const float4 w =
            *reinterpret_cast<const float4*>(&Wp[(k0 + kk) * C_ + c4]);
#pragma unroll
        for (int b = 0; b < B_; b++) {
            const float a = s_vv[kk * B_ + b];
            acc[b].x += a * w.x;
            acc[b].y += a * w.y;
            acc[b].z += a * w.z;
            acc[b].w += a * w.w;
        }
    }
#pragma unroll
    for (int b = 0; b < B_; b++)
        *reinterpret_cast<float4*>(&g_part2[(ks * B_ + b) * C_ + c4]) = acc[b];
}

// ---------------------------------------------------------------------------
// Kernel 3: r[b][c] = bp[c] + sum_p part2[p][b][c].   grid 16, block 256
// 4 threads per (b,c4) pair, each sums 32 partials; fixed-order smem tree.
// ---------------------------------------------------------------------------
__global__ void ca_reduce2(const float* __restrict__ bp) {
    __shared__ float4 sm[256];
    const int g = blockIdx.x * 256 + threadIdx.x;   // 0..4095
    const int pair = g >> 2;                         // 0..1023 = (b, c4-group)
    const int sub  = g & 3;
    const int b  = pair >> 8;
    const int c4 = (pair & 255) * 4;

    float4 s = make_float4(0.f, 0.f, 0.f, 0.f);
#pragma unroll
    for (int i = 0; i < 32; i++) {
        const int p = sub * 32 + i;
        const float4 v =
            *reinterpret_cast<const float4*>(&g_part2[(p * B_ + b) * C_ + c4]);
        s.x += v.x; s.y += v.y; s.z += v.z; s.w += v.w;
    }
    sm[threadIdx.x] = s;
    __syncthreads();

    if (sub == 0) {
        float4 r = *reinterpret_cast<const float4*>(&bp[c4]);
#pragma unroll
        for (int j = 0; j < 4; j++) {
            const float4 v = sm[threadIdx.x + j];
            r.x += v.x; r.y += v.y; r.z += v.z; r.w += v.w;
        }
        *reinterpret_cast<float4*>(&g_r[b * C_ + c4]) = r;
    }
}

// ---------------------------------------------------------------------------
// Kernel 4: broadcast r to all T rows.  grid (1, T_/TT_, B_), block 256
// ---------------------------------------------------------------------------
__global__ void ca_bcast(float* __restrict__ out) {
    const int b  = blockIdx.z;
    const int t0 = blockIdx.y * TT_;
    const int c4 = threadIdx.x * 4;

    const float4 r = *reinterpret_cast<const float4*>(&g_r[b * C_ + c4]);
#pragma unroll
    for (int t = 0; t < TT_; t++)
        *reinterpret_cast<float4*>(&out[((b * T_) + t0 + t) * C_ + c4]) = r;
}

// ---------------------------------------------------------------------------
// Inputs: 0 x, 1 vf, 2 Wq, 3 bq, 4 Wk, 5 bk, 6 Wv, 7 bv, 8 Wp, 9 bp
// ---------------------------------------------------------------------------
extern "C" void kernel_launch(void* const* d_in, const int* in_sizes, int n_in,
                              void* d_out, int out_size) {
    const float* vf = (const float*)d_in[1];
    const float* Wv = (const float*)d_in[6];
    const float* bv = (const float*)d_in[7];
    const float* Wp = (const float*)d_in[8];
    const float* bp = (const float*)d_in[9];
    float* out = (float*)d_out;

    ca_gemm1<<<KS_, 256>>>(vf, Wv);
    ca_gemm2<<<KS_, 256>>>(bv, Wp);
    ca_reduce2<<<16, 256>>>(bp);
    ca_bcast<<<dim3(1, T_ / TT_, B_), 256>>>(out);
}

// round 5
// speedup vs baseline: 1.1196x; 1.1196x over previous
#include <cuda_runtime.h>
#include <cstdint>

// out[b,t,:] = ((vf[b] @ Wv + bv) @ Wp + bp), broadcast over t.
// (keys/values broadcast over T -> softmax uniform -> y == v; x/Wq/Wk drop out)
//
// Single fused persistent kernel, 128 blocks (<= SM count, co-resident):
//   Phase A: GEMV1  vv_part[kh][b][c] (column-stripe split, in-block k reduce)
//   barrier
//   Phase B: GEMV2  r_part[kh][b][c]  (folds vv partials + bv at staging)
//   barrier
//   Phase C: fold r partials + bp, broadcast 16MB via TMA bulk stores
// All float reductions are fixed-order (deterministic).

#define C_     1024
#define B_     4
#define T_     1024
#define GRID_  128
#define NWORK_ 64    // 32 c-stripes x 2 k-halves

__device__ float g_vv_part[2][B_][C_];
__device__ float g_r_part[2][B_][C_];
__device__ unsigned g_barcnt[2];     // monotonic across graph replays

// Grid-wide barrier: monotonic counter, round = old/GRID_ (replay-safe, wrap-safe).
__device__ __forceinline__ void grid_barrier(int i) {
    __syncthreads();
    if (threadIdx.x == 0) {
        __threadfence();
        unsigned old = atomicAdd(&g_barcnt[i], 1u);
        unsigned target = (old / GRID_ + 1u) * GRID_;
        while ((int)(*(volatile unsigned*)&g_barcnt[i] - target) < 0)
            __nanosleep(32);
        __threadfence();
    }
    __syncthreads();
}

// One GEMV half: this block covers columns [c0, c0+32) and k-half kh.
// 8 warps split the 512 k-rows; in-block fixed-order reduce; write partial.
__device__ __forceinline__ void gemv_half(
    const float* __restrict__ W,
    const float (&s_in)[B_][512],
    float (&s_red)[8][B_][32],
    int kh, int c0,
    float (*out_part)[C_])      // g_xx_part[kh] : [B_][C_]
{
    const int lane = threadIdx.x & 31;
    const int w    = threadIdx.x >> 5;
    const int kg0  = kh * 512 + w * 64;   // global k base for this warp
    const int kl0  = w * 64;              // local  k base in s_in

    float acc0 = 0.f, acc1 = 0.f, acc2 = 0.f, acc3 = 0.f;
    const float* wp = &W[(size_t)kg0 * C_ + c0 + lane];

#pragma unroll
    for (int kk = 0; kk < 64; kk += 4) {
        const float wr0 = wp[(kk + 0) * C_];
        const float wr1 = wp[(kk + 1) * C_];
        const float wr2 = wp[(kk + 2) * C_];
        const float wr3 = wp[(kk + 3) * C_];
        const float4 a0 = *(const float4*)&s_in[0][kl0 + kk];
        const float4 a1 = *(const float4*)&s_in[1][kl0 + kk];
        const float4 a2 = *(const float4*)&s_in[2][kl0 + kk];
        const float4 a3 = *(const float4*)&s_in[3][kl0 + kk];
        acc0 += a0.x * wr0; acc0 += a0.y * wr1; acc0 += a0.z * wr2; acc0 += a0.w * wr3;
        acc1 += a1.x * wr0; acc1 += a1.y * wr1; acc1 += a1.z * wr2; acc1 += a1.w * wr3;
        acc2 += a2.x * wr0; acc2 += a2.y * wr1; acc2 += a2.z * wr2; acc2 += a2.w * wr3;
        acc3 += a3.x * wr0; acc3 += a3.y * wr1; acc3 += a3.z * wr2; acc3 += a3.w * wr3;
    }

    s_red[w][0][lane] = acc0;
    s_red[w][1][lane] = acc1;
    s_red[w][2][lane] = acc2;
    s_red[w][3][lane] = acc3;
    __syncthreads();
    if (w < B_) {   // warp w finalizes batch b == w
        float s = 0.f;
#pragma unroll
        for (int ww = 0; ww < 8; ww++) s += s_red[ww][w][lane];
        out_part[w][c0 + lane] = s;
    }
}

__global__ void __launch_bounds__(256, 1) ca_fused(
    const float* __restrict__ vf, const float* __restrict__ Wv,
    const float* __restrict__ bv, const float* __restrict__ Wp,
    const float* __restrict__ bp, float* __restrict__ out)
{
    __shared__ __align__(16) float  s_in[B_][512];
    __shared__ float  s_red[8][B_][32];
    __shared__ __align__(16) float4 s_row[256];

    const int bid = blockIdx.x;
    const int tid = threadIdx.x;

    // ---- Phase A: vv_part[kh][b][c] = sum_{k in half} vf[b,k] * Wv[k,c] ----
    if (bid < NWORK_) {
        const int kh = bid & 1;
        const int c0 = (bid >> 1) * 32;
        for (int i = tid; i < B_ * 512; i += 256) {
            const int b = i >> 9, kk = i & 511;
            s_in[b][kk] = vf[b * C_ + kh * 512 + kk];
        }
        __syncthreads();
        gemv_half(Wv, s_in, s_red, kh, c0, g_vv_part[kh]);
    }
    grid_barrier(0);

    // ---- Phase B: fold vv partials + bv, then r_part = vv @ Wp (half) ----
    if (bid < NWORK_) {
        const int kh = bid & 1;
        const int c0 = (bid >> 1) * 32;
        for (int i = tid; i < B_ * 512; i += 256) {
            const int b = i >> 9, kk = i & 511;
            const int K = kh * 512 + kk;
            s_in[b][kk] = g_vv_part[0][b][K] + g_vv_part[1][b][K] + bv[K];
        }
        __syncthreads();
        gemv_half(Wp, s_in, s_red, kh, c0, g_r_part[kh]);
    }
    grid_barrier(1);

    // ---- Phase C: r = p0 + p1 + bp; broadcast 32 rows via TMA bulk stores ----
    const int b  = bid >> 5;
    const int t0 = (bid & 31) * 32;
    {
        const int c4 = tid * 4;
        float4 r = *(const float4*)&bp[c4];
        const float4 p0 = *(const float4*)&g_r_part[0][b][c4];
        const float4 p1 = *(const float4*)&g_r_part[1][b][c4];
        r.x += p0.x + p1.x;
        r.y += p0.y + p1.y;
        r.z += p0.z + p1.z;
        r.w += p0.w + p1.w;
        s_row[tid] = r;
    }
    __syncthreads();

    if (tid == 0) {
        asm volatile("fence.proxy.async.shared::cta;" ::: "memory");
        const uint32_t saddr = (uint32_t)__cvta_generic_to_shared(s_row);
#pragma unroll
        for (int t = 0; t < 32; t++) {
            const float* dst = &out[(size_t)(b * T_ + t0 + t) * C_];
            asm volatile(
                "cp.async.bulk.global.shared::cta.bulk_group [%0], [%1], %2;"
                :: "l"(dst), "r"(saddr), "r"(4096) : "memory");
        }
        asm volatile("cp.async.bulk.commit_group;" ::: "memory");
        asm volatile("cp.async.bulk.wait_group 0;" ::: "memory");
    }
}

// Inputs: 0 x, 1 vf, 2 Wq, 3 bq, 4 Wk, 5 bk, 6 Wv, 7 bv, 8 Wp, 9 bp
extern "C" void kernel_launch(void* const* d_in, const int* in_sizes, int n_in,
                              void* d_out, int out_size) {
    const float* vf = (const float*)d_in[1];
    const float* Wv = (const float*)d_in[6];
    const float* bv = (const float*)d_in[7];
    const float* Wp = (const float*)d_in[8];
    const float* bp = (const float*)d_in[9];
    float* out = (float*)d_out;

    ca_fused<<<GRID_, 256>>>(vf, Wv, bv, Wp, bp, out);
}

// round 8
// speedup vs baseline: 1.4975x; 1.3375x over previous
#include <cuda_runtime.h>
#include <cstdint>

// out[b,t,:] = ((vf[b] @ Wv + bv) @ Wp + bp), broadcast over t.
// (keys/values broadcast over T -> softmax uniform -> y == v; x/Wq/Wk drop out)
//
// Single fused persistent kernel, 128 blocks x 512 threads:
//   work item = (slab of 128 cols, k-chunk of 64 rows): 8 x 16 = 128 blocks.
//   Phase A: g_p1[kc][b][c] = sum_{k in chunk} vf[b,k] * Wv[k,c]   (LDG.128, MLP4/warp)
//   barrier
//   Phase B: stage vv = fold16(g_p1)+bv  (L2), then g_p2 = vv-chunk @ Wp
//   barrier
//   Phase C: r = fold16(g_p2)+bp (L2); broadcast 32 rows via TMA bulk (32 lanes dispatch)
// All float reductions fixed-order (deterministic).

#define C_     1024
#define B_     4
#define T_     1024
#define GRID_  128
#define BLOCK_ 512
#define NKC_   16     // k-chunks
#define KCH_   64     // rows per k-chunk
#define NSLAB_ 8      // column slabs
#define SLABW_ 128    // columns per slab

__device__ float g_p1[NKC_][B_][C_];   // 256 KB, L2-resident
__device__ float g_p2[NKC_][B_][C_];   // 256 KB
__device__ unsigned g_barcnt[2];       // monotonic across graph replays

// Grid-wide barrier: monotonic counter (replay-safe, wrap-safe).
__device__ __forceinline__ void grid_barrier(int i) {
    __syncthreads();
    if (threadIdx.x == 0) {
        __threadfence();
        unsigned old = atomicAdd(&g_barcnt[i], 1u);
        unsigned target = (old / GRID_ + 1u) * GRID_;
        while ((int)(*(volatile unsigned*)&g_barcnt[i] - target) < 0)
            __nanosleep(32);
        __threadfence();
    }
    __syncthreads();
}

// One GEMV tile: 64 k-rows (k0) x 128 cols (slab). Warp w loads rows k0+4w..+3
// as 4 independent LDG.128; in-block fixed-order smem reduce; write partial.
__device__ __forceinline__ void gemv_tile(
    const float* __restrict__ W,
    const float (&s_in)[B_][KCH_],
    float (&s_red)[16][B_][SLABW_],
    int k0, int slab, int tid,
    float* __restrict__ gout)          // g_pX[kc] : [B_][C_] flat
{
    const int lane = tid & 31;
    const int w    = tid >> 5;
    const int kw   = w * 4;                       // local row base
    const int col  = slab * SLABW_ + lane * 4;

    const float* wp = &W[(size_t)(k0 + kw) * C_ + col];
    const float4 w0 = *(const float4*)(wp);
    const float4 w1 = *(const float4*)(wp + C_);
    const float4 w2 = *(const float4*)(wp + 2 * C_);
    const float4 w3 = *(const float4*)(wp + 3 * C_);

#pragma unroll
    for (int b = 0; b < B_; b++) {
        const float a0 = s_in[b][kw + 0];
        const float a1 = s_in[b][kw + 1];
        const float a2 = s_in[b][kw + 2];
        const float a3 = s_in[b][kw + 3];
        float4 acc;
        acc.x = a0 * w0.x + a1 * w1.x + a2 * w2.x + a3 * w3.x;
        acc.y = a0 * w0.y + a1 * w1.y + a2 * w2.y + a3 * w3.y;
        acc.z = a0 * w0.z + a1 * w1.z + a2 * w2.z + a3 * w3.z;
        acc.w = a0 * w0.w + a1 * w1.w + a2 * w2.w + a3 * w3.w;
        *(float4*)&s_red[w][b][lane * 4] = acc;
    }
    __syncthreads();

    // 512 threads: (b, c) = (tid>>7, tid&127); fixed-order sum over 16 warps
    const int rb = tid >> 7;
    const int rc = tid & 127;
    float s = 0.f;
#pragma unroll
    for (int ww = 0; ww < 16; ww++) s += s_red[ww][rb][rc];
    gout[rb * C_ + slab * SLABW_ + rc] = s;
}

__global__ void __launch_bounds__(BLOCK_, 1) ca_fused(
    const float* __restrict__ vf, const float* __restrict__ Wv,
    const float* __restrict__ bv, const float* __restrict__ Wp,
    const float* __restrict__ bp, float* __restrict__ out)
{
    __shared__ __align__(16) float s_in[B_][KCH_];            // 1 KB
    __shared__ __align__(16) float s_red[16][B_][SLABW_];     // 32 KB
    __shared__ __align__(16) float s_row[C_];                 // 4 KB

    const int bid  = blockIdx.x;
    const int tid  = threadIdx.x;
    const int slab = bid & (NSLAB_ - 1);
    const int kc   = bid >> 3;
    const int k0   = kc * KCH_;

    // ---- Phase A: g_p1[kc] = vf-chunk @ Wv-tile ----
    if (tid < B_ * KCH_) {
        const int b = tid >> 6, j = tid & 63;
        s_in[b][j] = vf[b * C_ + k0 + j];
    }
    __syncthreads();
    gemv_tile(Wv, s_in, s_red, k0, slab, tid, &g_p1[kc][0][0]);
    grid_barrier(0);

    // ---- Phase B: stage vv chunk (fold 16 partials + bv), then @ Wp-tile ----
    if (tid < B_ * KCH_) {
        const int b = tid >> 6, j = tid & 63;
        const int K = k0 + j;
        float s = bv[K];
#pragma unroll
        for (int p = 0; p < NKC_; p++) s += g_p1[p][b][K];
        s_in[b][j] = s;
    }
    __syncthreads();
    gemv_tile(Wp, s_in, s_red, k0, slab, tid, &g_p2[kc][0][0]);
    grid_barrier(1);

    // ---- Phase C: r[b] = fold 16 partials + bp; TMA-broadcast 32 rows ----
    const int b  = bid >> 5;
    const int t0 = (bid & 31) * 32;
    if (tid < 256) {
        const int c4 = tid * 4;
        float4 r = *(const float4*)&bp[c4];
#pragma unroll
        for (int p = 0; p < NKC_; p++) {
            const float4 v = *(const float4*)&g_p2[p][b][c4];
            r.x += v.x; r.y += v.y; r.z += v.z; r.w += v.w;
        }
        *(float4*)&s_row[c4] = r;
    }
    __syncthreads();

    if (tid < 32) {
        asm volatile("fence.proxy.async.shared::cta;" ::: "memory");
        const uint32_t saddr = (uint32_t)__cvta_generic_to_shared(s_row);
        const float* dst = &out[(size_t)(b * T_ + t0 + tid) * C_];
        asm volatile(
            "cp.async.bulk.global.shared::cta.bulk_group [%0], [%1], %2;"
            :: "l"(dst), "r"(saddr), "r"(4096) : "memory");
        asm volatile("cp.async.bulk.commit_group;" ::: "memory");
        asm volatile("cp.async.bulk.wait_group 0;" ::: "memory");
    }
}

// Inputs: 0 x, 1 vf, 2 Wq, 3 bq, 4 Wk, 5 bk, 6 Wv, 7 bv, 8 Wp, 9 bp
extern "C" void kernel_launch(void* const* d_in, const int* in_sizes, int n_in,
                              void* d_out, int out_size) {
    const float* vf = (const float*)d_in[1];
    const float* Wv = (const float*)d_in[6];
    const float* bv = (const float*)d_in[7];
    const float* Wp = (const float*)d_in[8];
    const float* bp = (const float*)d_in[9];
    float* out = (float*)d_out;

    ca_fused<<<GRID_, BLOCK_>>>(vf, Wv, bv, Wp, bp, out);
}